// round 15
// baseline (speedup 1.0000x reference)
#include <cuda_runtime.h>

#define WIDTH   512
#define HEIGHT  512
#define TW      256                // tile width (x-split)
#define TH      8                  // output rows per CTA
#define NTH     256                // threads per CTA
// SMEM row: 262 tuples (256 px + 3 apron each side) padded to 264 (x16B).
// ROWB multiple of 128 keeps swizzle-group alignment across rows.
#define ROWT    264
#define ROWB    (ROWT * 16)        // 4224 bytes
#define SMEM_BYTES (TH * ROWB)     // 33792 -> 4 CTAs/SM

typedef unsigned long long u64;

// reflect padding (pad=3 < dim, single reflection suffices)
__device__ __forceinline__ int refl(int i, int n) {
    i = i < 0 ? -i : i;
    return i >= n ? 2 * n - 2 - i : i;
}

// XOR swizzle: byte offset of tuple #t within an SMEM row.
__device__ __forceinline__ unsigned vboff(int t) {
    return (unsigned)((t ^ ((t >> 3) & 7)) << 4);
}

__device__ __forceinline__ u64 pack2(float lo, float hi) {
    u64 r; asm("mov.b64 %0, {%1, %2};" : "=l"(r) : "f"(lo), "f"(hi)); return r;
}
__device__ __forceinline__ void unpack2(u64 v, float& lo, float& hi) {
    asm("mov.b64 {%0, %1}, %2;" : "=f"(lo), "=f"(hi) : "l"(v));
}
// packed dual FMA -> FFMA2 in SASS (PTX-only form)
__device__ __forceinline__ u64 fma2(u64 a, u64 b, u64 c) {
    u64 d; asm("fma.rn.f32x2 %0, %1, %2, %3;" : "=l"(d) : "l"(a), "l"(b), "l"(c));
    return d;
}
__device__ __forceinline__ float frsq_ap(float x) {
    float r; asm("rsqrt.approx.f32 %0, %1;" : "=f"(r) : "f"(x)); return r;
}

// Stage-1 vertical blur for one column (global x = gx, already x-reflected).
// EDGE=false: zero per-row address ALU (immediate-offset LDGs).
template<bool EDGE>
__device__ __forceinline__ void stage1_col(const float* __restrict__ cp,
                                           const float* __restrict__ sp,
                                           unsigned char* sm,
                                           int gx, unsigned sb,
                                           int y0, const u64* G2) {
    u64 rc[7], rs[7];                          // ring: packed (v, v^2)
    const float* cr = cp + (y0 - 3) * WIDTH + gx;  // valid base when !EDGE
    const float* sr = sp + (y0 - 3) * WIDTH + gx;
    #pragma unroll
    for (int i = 0; i < TH + 6; ++i) {
        float c, s;
        if (EDGE) {
            const int gy = refl(y0 - 3 + i, HEIGHT);
            c = __ldg(cp + gy * WIDTH + gx);
            s = __ldg(sp + gy * WIDTH + gx);
        } else {
            c = __ldg(cr + i * WIDTH);         // LDG [R + imm]
            s = __ldg(sr + i * WIDTH);
        }
        rc[i % 7] = pack2(c, c * c);
        rs[i % 7] = pack2(s, s * s);
        if (i >= 6) {
            const int o = i - 6;               // output row within tile
            u64 a = 0ull, d = 0ull;            // (mean, E2) packed per tensor
            #pragma unroll
            for (int k = 0; k < 7; ++k) {
                const int q = (o + k) % 7;     // compile-time after unroll
                a = fma2(G2[k], rc[q], a);
                d = fma2(G2[k], rs[q], d);
            }
            ulonglong2 v; v.x = a; v.y = d;
            *reinterpret_cast<ulonglong2*>(sm + o * ROWB + sb) = v;
        }
    }
}

__global__ __launch_bounds__(NTH, 4)
void adain_local_kernel(const float* __restrict__ content,
                        const float* __restrict__ style,
                        float* __restrict__ out) {
    extern __shared__ unsigned char sm[];

    const float G[7] = {0.0044330481752437f, 0.0540055826224143f,
                        0.2420362293761143f, 0.3990502746173879f,
                        0.2420362293761143f, 0.0540055826224143f,
                        0.0044330481752437f};
    u64 G2[7];
    #pragma unroll
    for (int k = 0; k < 7; ++k) G2[k] = pack2(G[k], G[k]);

    const int plane = blockIdx.z;
    const int x0    = blockIdx.y * TW;        // 0 or 256
    const int y0    = blockIdx.x * TH;
    const size_t pb = (size_t)plane * (WIDTH * HEIGHT);
    const float* cp = content + pb;
    const float* sp = style   + pb;
    float*       op = out     + pb;
    const int tid = threadIdx.x;

    // -------- Stage 1: vertical 7-tap blur over 262 columns -----------------
    // column cl in [0,261] -> global x = refl(x0 - 3 + cl) (x-apron baked in;
    // once-per-column cost). Threads 0..5 take the 6 tail columns too.
    {
        const int gx  = refl(x0 - 3 + tid, WIDTH);
        const unsigned sb = vboff(tid);
        if (y0 >= 3 && y0 + TH + 3 <= HEIGHT) {
            stage1_col<false>(cp, sp, sm, gx, sb, y0, G2);
            if (tid < 6)
                stage1_col<false>(cp, sp, sm, refl(x0 - 3 + TW + tid, WIDTH),
                                  vboff(TW + tid), y0, G2);
        } else {
            stage1_col<true >(cp, sp, sm, gx, sb, y0, G2);
            if (tid < 6)
                stage1_col<true >(cp, sp, sm, refl(x0 - 3 + TW + tid, WIDTH),
                                  vboff(TW + tid), y0, G2);
        }
    }
    __syncthreads();

    // ---- Stage 2: horizontal 7-tap + AdaIN epilogue; 1 task per thread -----
    // 256 tasks = TH(8) rows x 32 chunks of 8 px. Window tuple index = 8l + j
    // (aprons in-row), so no reflection logic at all here.
    {
        const int row = tid >> 5;              // 0..7
        const int l   = tid & 31;              // chunk id within tile
        const int gy  = y0 + row;
        const int gxc = x0 + (l << 3);         // global chunk start column
        const unsigned char* smrow = sm + row * ROWB;
        const int tb = l << 3;                 // base tuple index = 8l

        // hoist raw-content loads (overlap latency with the FFMA2 stream)
        const float4 cA = *reinterpret_cast<const float4*>(cp + gy * WIDTH + gxc);
        const float4 cB = *reinterpret_cast<const float4*>(cp + gy * WIDTH + gxc + 4);

        u64 ac[8], as_[8];                     // packed accumulators per pixel
        #pragma unroll
        for (int o = 0; o < 8; ++o) { ac[o] = 0ull; as_[o] = 0ull; }

        #pragma unroll
        for (int j = 0; j < 14; ++j) {
            const ulonglong2 w =
                *reinterpret_cast<const ulonglong2*>(smrow + vboff(tb + j));
            #pragma unroll
            for (int o = 0; o < 8; ++o) {
                const int k = j - o;
                if (k >= 0 && k < 7) {         // compile-time predicate
                    ac[o]  = fma2(G2[k], w.x, ac[o]);
                    as_[o] = fma2(G2[k], w.y, as_[o]);
                }
            }
        }

        const float craw[8] = {cA.x, cA.y, cA.z, cA.w, cB.x, cB.y, cB.z, cB.w};

        float res[8];
        #pragma unroll
        for (int o = 0; o < 8; ++o) {
            float cm, cE2, smn, sE2;
            unpack2(ac[o],  cm,  cE2);
            unpack2(as_[o], smn, sE2);
            const float cv = fmaxf(fmaf(-cm,  cm,  cE2), 1e-6f);
            const float sv = fmaxf(fmaf(-smn, smn, sE2), 1e-6f);
            const float rqc = frsq_ap(cv);              // MUFU.RSQ (parallel)
            const float rqs = frsq_ap(sv);              // MUFU.RSQ (parallel)
            const float numer = fmaf(sv, rqs, 1e-5f);   // sqrt(sv) + eps
            const float dinv  = rqc - (1e-5f * rqc) * rqc; // ~1/(sqrt(cv)+eps)
            res[o] = fmaf(craw[o] - cm, numer * dinv, smn);
        }

        *reinterpret_cast<float4*>(op + gy * WIDTH + gxc) =
            make_float4(res[0], res[1], res[2], res[3]);
        *reinterpret_cast<float4*>(op + gy * WIDTH + gxc + 4) =
            make_float4(res[4], res[5], res[6], res[7]);
    }
}

extern "C" void kernel_launch(void* const* d_in, const int* in_sizes, int n_in,
                              void* d_out, int out_size) {
    const float* content = (const float*)d_in[0];
    const float* style   = (const float*)d_in[1];
    float*       out     = (float*)d_out;

    const int planes = in_sizes[0] / (WIDTH * HEIGHT);   // 4*64 = 256

    cudaFuncSetAttribute(adain_local_kernel,
                         cudaFuncAttributeMaxDynamicSharedMemorySize, SMEM_BYTES);

    dim3 grid(HEIGHT / TH, WIDTH / TW, planes);          // 64 x 2 x 256
    adain_local_kernel<<<grid, NTH, SMEM_BYTES>>>(content, style, out);
}